// round 13
// baseline (speedup 1.0000x reference)
#include <cuda_runtime.h>

// GRU persistent v7: v5 tiles + per-warp async gathers + per-warp monotonic
// group barrier (no release hop, no block-wide resync). 2 halves per CTA.
#define SEQLEN 512
#define HPADF  260
#define XPADF  132
#define WT4    1536
#define QBLK   12480

__device__ float              g_h [256 * 256];
__device__ float              g_rh[256 * 256];
__device__ unsigned long long g_cnt[16 * 16];   // 16 groups, 128B apart

__device__ __forceinline__ void ffma2(unsigned long long &a,
                                      unsigned long long x, unsigned long long y) {
    asm("fma.rn.f32x2 %0, %1, %2, %0;" : "+l"(a) : "l"(x), "l"(y));
}
__device__ __forceinline__ float f2sum(unsigned long long v) {
    return __uint_as_float((unsigned)v) + __uint_as_float((unsigned)(v >> 32));
}
__device__ __forceinline__ float sig_(float a) { return 1.0f / (1.0f + __expf(-a)); }
__device__ __forceinline__ float tanh_(float a) { return 2.0f / (1.0f + __expf(-2.0f * a)) - 1.0f; }
__device__ __forceinline__ void barn(int id) {
    asm volatile("bar.sync %0, 128;" :: "r"(id) : "memory");
}

#define ACC2(a, wv, hv) { ffma2(a, (wv).x, (hv).x); ffma2(a, (wv).y, (hv).y); }
#define ZR16(v0,v1,v2,v3,z0,z1,r0,r1) \
    ACC2(az[0],z0,v0); ACC2(az[1],z1,v0); ACC2(az[2],z0,v1); ACC2(az[3],z1,v1); \
    ACC2(az[4],z0,v2); ACC2(az[5],z1,v2); ACC2(az[6],z0,v3); ACC2(az[7],z1,v3); \
    ACC2(ar[0],r0,v0); ACC2(ar[1],r1,v0); ACC2(ar[2],r0,v1); ACC2(ar[3],r1,v1); \
    ACC2(ar[4],r0,v2); ACC2(ar[5],r1,v2); ACC2(ar[6],r0,v3); ACC2(ar[7],r1,v3);
#define C8(v0,v1,v2,v3,c0,c1) \
    ACC2(ac[0],c0,v0); ACC2(ac[1],c1,v0); ACC2(ac[2],c0,v1); ACC2(ac[3],c1,v1); \
    ACC2(ac[4],c0,v2); ACC2(ac[5],c1,v2); ACC2(ac[6],c0,v3); ACC2(ac[7],c1,v3);

// warp-scope arrive: all lanes' prior STG ordered before lane0's atomic
#define WARP_ARRIVE(cnt, l) { __syncwarp(); __threadfence(); \
    if ((l) == 0) atomicAdd((cnt), 1ull); }
// warp-scope wait on monotonic counter
#define WARP_WAIT(cnt, l, base, bidx) { \
    if ((l) == 0) { \
        while (*((volatile unsigned long long *)(cnt)) - (base) < 64ull * (bidx)) { } \
        __threadfence(); \
    } \
    __syncwarp(); }

__global__ void __launch_bounds__(256, 1)
gru_persistent(const float* __restrict__ X,
               const float* __restrict__ Wz, const float* __restrict__ bz,
               const float* __restrict__ Wr, const float* __restrict__ br,
               const float* __restrict__ Wc, const float* __restrict__ bc,
               float* __restrict__ out)
{
    extern __shared__ float sm[];
    float* wT = sm;                       // 18432 floats, k-major interleaved
    float* sB = sm + 18432;               // 48
    const int tid  = threadIdx.x;
    const int half = tid >> 7, lt = tid & 127;
    const int w = lt >> 5, l = lt & 31, rr = l & 3, cc = l >> 2;
    const int bt = blockIdx.x & 7, hsb = blockIdx.x >> 3;
    const int bbase = bt * 32 + half * 16, jbase = hsb * 16;
    const int nb = 1 + half;
    float* hb   = sm + 18480 + half * QBLK;
    float* h_s  = hb;                     // 16 x 260
    float* rh_s = hb + 4160;              // 16 x 260
    float* x_s  = hb + 8320;              // 16 x 132
    float* red  = hb + 10432;             // 2048

    unsigned long long* cnt = &g_cnt[(bt * 2 + half) * 16];
    unsigned long long base = 0;
    if (l == 0)   // snapshot; one replay advances each group counter by 65536
        base = (*((volatile unsigned long long *)cnt) / 65536ull) * 65536ull;

    {   // weights: k-major, col pairs interleaved (slot = (c>>1) + 8*(c&1))
        float4* wp = (float4*)wT;
        for (int idx = tid; idx < 3 * WT4; idx += 256) {
            int g = idx / WT4, rem = idx % WT4, k4 = rem >> 4, c = rem & 15;
            const float4* W4 = (const float4*)((g == 0) ? Wz : (g == 1) ? Wr : Wc);
            wp[(g * 96 + k4) * 16 + ((c >> 1) + 8 * (c & 1))] = W4[(jbase + c) * 96 + k4];
        }
        if (tid < 16) {
            sB[tid] = bz[jbase + tid]; sB[16 + tid] = br[jbase + tid];
            sB[32 + tid] = bc[jbase + tid];
        }
    }
    for (int i = lt; i < 16 * HPADF; i += 128) h_s[i] = 0.0f;   // h0 = 0
    {   // x(0): each warp loads its own x slice (warp-private cols [8w,8w+8))
        int grow = l & 15, gch = l >> 4;
        #pragma unroll
        for (int j = 0; j < 4; j++) {
            int c4 = 8 * w + 4 * gch + j;
            *(float4*)(x_s + grow * XPADF + c4 * 4) =
                ((const float4*)X)[(size_t)(bbase + grow) * (SEQLEN * 32) + c4];
        }
    }
    __syncthreads();

    const ulonglong2* hA = (const ulonglong2*)(h_s + rr * HPADF);
    const ulonglong2* hB = (const ulonglong2*)(h_s + (rr + 4) * HPADF);
    const ulonglong2* hC = (const ulonglong2*)(h_s + (rr + 8) * HPADF);
    const ulonglong2* hD = (const ulonglong2*)(h_s + (rr + 12) * HPADF);
    const ulonglong2* rA = (const ulonglong2*)(rh_s + rr * HPADF);
    const ulonglong2* rB = (const ulonglong2*)(rh_s + (rr + 4) * HPADF);
    const ulonglong2* rC = (const ulonglong2*)(rh_s + (rr + 8) * HPADF);
    const ulonglong2* rD = (const ulonglong2*)(rh_s + (rr + 12) * HPADF);
    const ulonglong2* xA = (const ulonglong2*)(x_s + rr * XPADF);
    const ulonglong2* xB = (const ulonglong2*)(x_s + (rr + 4) * XPADF);
    const ulonglong2* xC = (const ulonglong2*)(x_s + (rr + 8) * XPADF);
    const ulonglong2* xD = (const ulonglong2*)(x_s + (rr + 12) * XPADF);
    const ulonglong2* wzp = (const ulonglong2*)wT + cc;
    const ulonglong2* wrp = wzp + WT4;
    const ulonglong2* wcp = wzp + 2 * WT4;
    const int kw = w * 16, kx = w * 8, sw = w ^ rr;
    const int orow0 = lt >> 4, ocol = lt & 15, orow1 = orow0 + 8;
    const float bzv = sB[ocol], brv = sB[16 + ocol], bcv = sB[32 + ocol];
    const int grow = l & 15, gch = l >> 4;      // gather lane map (conflict-free)

    unsigned long long az[8], ar[8], ac[8];
    #pragma unroll
    for (int i = 0; i < 8; i++) { az[i] = 0; ar[i] = 0; }

    // anti-phase stagger: half 1 runs 2 dummy phase1-h passes on zeroed h_s
    // (adds exact zeros to az/ar — numeric identity, offsets the halves).
    if (half == 1) {
        #pragma unroll 1
        for (int d = 0; d < 2; d++) {
            #pragma unroll 4
            for (int kk = 0; kk < 16; kk++) {
                int k4 = kw + kk;
                ulonglong2 v0 = hA[k4], v1 = hB[k4], v2 = hC[k4], v3 = hD[k4];
                ulonglong2 z0 = wzp[k4*16], z1 = wzp[k4*16+8];
                ulonglong2 r0 = wrp[k4*16], r1 = wrp[k4*16+8];
                ZR16(v0,v1,v2,v3,z0,z1,r0,r1)
            }
        }
    }

    unsigned long long bidx = 0;

    for (int t = 0; t < SEQLEN; t++) {
        // ---- phase1 x-part (covers part of B-barrier latency) ----
        #pragma unroll 4
        for (int kk = 0; kk < 8; kk++) {
            int k4 = 64 + kx + kk, kq = kx + kk;
            ulonglong2 v0 = xA[kq], v1 = xB[kq], v2 = xC[kq], v3 = xD[kq];
            ulonglong2 z0 = wzp[k4*16], z1 = wzp[k4*16+8];
            ulonglong2 r0 = wrp[k4*16], r1 = wrp[k4*16+8];
            ZR16(v0,v1,v2,v3,z0,z1,r0,r1)
        }
        // ---- B-wait (prev step) + per-warp h gather of own k-slice ----
        if (t > 0) {
            WARP_WAIT(cnt, l, base, bidx)
            float4 tmp[8];
            #pragma unroll
            for (int j = 0; j < 8; j++) {
                int c4 = 16 * w + 8 * gch + j;
                tmp[j] = ((const float4*)g_h)[(bbase + grow) * 64 + c4];
            }
            #pragma unroll
            for (int j = 0; j < 8; j++) {
                int c4 = 16 * w + 8 * gch + j;
                *(float4*)(h_s + grow * HPADF + c4 * 4) = tmp[j];
            }
            __syncwarp();
        }
        // ---- phase1 h-part (own k-slice only) ----
        #pragma unroll 4
        for (int kk = 0; kk < 16; kk++) {
            int k4 = kw + kk;
            ulonglong2 v0 = hA[k4], v1 = hB[k4], v2 = hC[k4], v3 = hD[k4];
            ulonglong2 z0 = wzp[k4*16], z1 = wzp[k4*16+8];
            ulonglong2 r0 = wrp[k4*16], r1 = wrp[k4*16+8];
            ZR16(v0,v1,v2,v3,z0,z1,r0,r1)
        }
        #pragma unroll
        for (int i = 0; i < 4; i++)
            #pragma unroll
            for (int e = 0; e < 2; e++) {
                int o = (rr + 4*i) * 16 + 2*cc + e;
                red[(o << 2) + sw]         = f2sum(az[i*2+e]);
                red[((256 + o) << 2) + sw] = f2sum(ar[i*2+e]);
            }
        barn(nb);                                    // k-split reduction sync
        float4 p0 = *(float4*)(red + lt*4);
        float4 p1 = *(float4*)(red + (lt+128)*4);
        float4 p2 = *(float4*)(red + (lt+256)*4);
        float4 p3 = *(float4*)(red + (lt+384)*4);
        float zz0 = sig_(p0.x+p0.y+p0.z+p0.w + bzv);
        float zz1 = sig_(p1.x+p1.y+p1.z+p1.w + bzv);
        float rv0 = sig_(p2.x+p2.y+p2.z+p2.w + brv);
        float rv1 = sig_(p3.x+p3.y+p3.z+p3.w + brv);
        float h0o = h_s[orow0 * HPADF + jbase + ocol];
        float h1o = h_s[orow1 * HPADF + jbase + ocol];
        g_rh[(bbase + orow0) * 256 + jbase + ocol] = rv0 * h0o;
        g_rh[(bbase + orow1) * 256 + jbase + ocol] = rv1 * h1o;

        WARP_ARRIVE(cnt, l)  bidx++;                 // A arrive (per warp)

        #pragma unroll
        for (int i = 0; i < 8; i++) { az[i] = 0; ar[i] = 0; ac[i] = 0; }
        float4 xt[4];
        if (t + 1 < SEQLEN) {                        // prefetch x(t+1) to regs
            #pragma unroll
            for (int j = 0; j < 4; j++) {
                int c4 = 8 * w + 4 * gch + j;
                xt[j] = ((const float4*)X)[(size_t)(bbase + grow) * (SEQLEN * 32)
                                           + (size_t)(t + 1) * 32 + c4];
            }
        }
        #pragma unroll 4
        for (int kk = 0; kk < 8; kk++) {             // cand x-part (covers A)
            int k4 = 64 + kx + kk, kq = kx + kk;
            ulonglong2 v0 = xA[kq], v1 = xB[kq], v2 = xC[kq], v3 = xD[kq];
            ulonglong2 c0 = wcp[k4*16], c1 = wcp[k4*16+8];
            C8(v0,v1,v2,v3,c0,c1)
        }
        if (t + 1 < SEQLEN) {                        // park x(t+1) (warp-private)
            #pragma unroll
            for (int j = 0; j < 4; j++) {
                int c4 = 8 * w + 4 * gch + j;
                *(float4*)(x_s + grow * XPADF + c4 * 4) = xt[j];
            }
            __syncwarp();
        }

        WARP_WAIT(cnt, l, base, bidx)                // A wait (per warp)
        {   // per-warp rh gather of own k-slice
            float4 tmp[8];
            #pragma unroll
            for (int j = 0; j < 8; j++) {
                int c4 = 16 * w + 8 * gch + j;
                tmp[j] = ((const float4*)g_rh)[(bbase + grow) * 64 + c4];
            }
            #pragma unroll
            for (int j = 0; j < 8; j++) {
                int c4 = 16 * w + 8 * gch + j;
                *(float4*)(rh_s + grow * HPADF + c4 * 4) = tmp[j];
            }
            __syncwarp();
        }
        #pragma unroll 4
        for (int kk = 0; kk < 16; kk++) {            // phase2 h-part
            int k4 = kw + kk;
            ulonglong2 v0 = rA[k4], v1 = rB[k4], v2 = rC[k4], v3 = rD[k4];
            ulonglong2 c0 = wcp[k4*16], c1 = wcp[k4*16+8];
            C8(v0,v1,v2,v3,c0,c1)
        }
        #pragma unroll
        for (int i = 0; i < 4; i++)
            #pragma unroll
            for (int e = 0; e < 2; e++) {
                int o = (rr + 4*i) * 16 + 2*cc + e;
                red[(o << 2) + sw] = f2sum(ac[i*2+e]);
            }
        barn(nb);                                    // k-split reduction sync
        float4 q0 = *(float4*)(red + lt*4);
        float4 q1 = *(float4*)(red + (lt+128)*4);
        float c0v = tanh_(q0.x+q0.y+q0.z+q0.w + bcv);
        float c1v = tanh_(q1.x+q1.y+q1.z+q1.w + bcv);
        float hn0 = h0o + zz0 * (c0v - h0o);
        float hn1 = h1o + zz1 * (c1v - h1o);
        g_h[(bbase + orow0) * 256 + jbase + ocol] = hn0;
        g_h[(bbase + orow1) * 256 + jbase + ocol] = hn1;

        WARP_ARRIVE(cnt, l)  bidx++;                 // B arrive (per warp)

        out[((size_t)t * 256 + bbase + orow0) * 256 + jbase + ocol] = hn0;
        out[((size_t)t * 256 + bbase + orow1) * 256 + jbase + ocol] = hn1;
    }
}

extern "C" void kernel_launch(void* const* d_in, const int* in_sizes, int n_in,
                              void* d_out, int out_size) {
    const float* X  = (const float*)d_in[0];
    const float* Wz = (const float*)d_in[1];
    const float* bz = (const float*)d_in[2];
    const float* Wr = (const float*)d_in[3];
    const float* br = (const float*)d_in[4];
    const float* Wc = (const float*)d_in[5];
    const float* bc = (const float*)d_in[6];
    float* out = (float*)d_out;

    int smem_bytes = (18480 + 2 * QBLK) * (int)sizeof(float);   // 173,760 B
    cudaFuncSetAttribute(gru_persistent,
                         cudaFuncAttributeMaxDynamicSharedMemorySize, smem_bytes);
    gru_persistent<<<128, 256, smem_bytes>>>(X, Wz, bz, Wr, br, Wc, bc, out);
}